// round 2
// baseline (speedup 1.0000x reference)
#include <cuda_runtime.h>
#include <cstdint>

// ---------------------------------------------------------------------------
// VectorBasis: out[a,m,o] = sum_{edges e with center a}
//     fc(d_e) * Y_m(e) * sum_n R_n(d_e) * T[sc_a, sn_e, n, o]
// where T[sc,sn,n,o] = sum_q W_alch[sn,q] * emb[sc, n*4+q] * Wc[o, n*4+q]
//
// Scratch layout (stride 12, only 9 used, output-ordered):
//   scratch[a*12 + j] == out[a*9 + j],  j = m*3 + o
//   per-edge accumulation: red.v4 [j0..j3], red.v4 [j4..j7], red.f32 [j8]
//   -> exactly 9 atomic f32 adds per edge (was 12 with a pad lane)
// ---------------------------------------------------------------------------

#define A_MAX 100000
__device__ float g_scratch[A_MAX * 12];

__device__ __forceinline__ void red_add_v4(float* p, float a, float b, float c, float d) {
    asm volatile("red.global.add.v4.f32 [%0], {%1, %2, %3, %4};"
                 :: "l"(p), "f"(a), "f"(b), "f"(c), "f"(d)
                 : "memory");
}
__device__ __forceinline__ void red_add_f32(float* p, float a) {
    asm volatile("red.global.add.f32 [%0], %1;"
                 :: "l"(p), "f"(a)
                 : "memory");
}

__global__ void __launch_bounds__(256)
edge_kernel(const float* __restrict__ vecs,     // (E,3)
            const int*   __restrict__ centers,  // (E,)
            const int*   __restrict__ neighbors,// (E,)
            const int*   __restrict__ species,  // (A,)
            const float* __restrict__ W_alch,   // (4,4)
            const float* __restrict__ emb,      // (4,32)
            const float* __restrict__ Wc,       // (3,32)
            float*       __restrict__ scratch,  // (A,12)
            int E)
{
    // Per-species-pair contraction table, padded stride 25 (odd -> pair index
    // injective mod 32 banks -> conflict-free for lane-varying pairs).
    __shared__ float sT[16 * 25];
    for (int t = threadIdx.x; t < 16 * 24; t += blockDim.x) {
        int p = t / 24, r = t - p * 24;
        int n = r / 3,  o = r - n * 3;
        int sc = p >> 2, sn = p & 3;
        float v = 0.f;
#pragma unroll
        for (int q = 0; q < 4; q++) {
            int d = n * 4 + q;
            v = fmaf(W_alch[sn * 4 + q] * emb[sc * 32 + d], Wc[o * 32 + d], v);
        }
        sT[p * 25 + r] = v;
    }
    __syncthreads();

    int e = blockIdx.x * blockDim.x + threadIdx.x;
    if (e >= E) return;

    float vx = vecs[e * 3 + 0];
    float vy = vecs[e * 3 + 1];
    float vz = vecs[e * 3 + 2];

    float d2   = fmaf(vx, vx, fmaf(vy, vy, vz * vz)) + 1e-12f;
    float invd = rsqrtf(d2);
    float d    = d2 * invd;

    int a  = centers[e];
    int sc = species[a];
    int sn = species[neighbors[e]];
    const float* T = &sT[(sc * 4 + sn) * 25];

    // R_n = sin(n*pi*d/rc)/d via Chebyshev recurrence, invd folded into r1
    float th = 0.62831853071795864769f * d; // pi/5 * d
    float s, c;
    __sincosf(th, &s, &c);
    float twoc = 2.0f * c;
    float r_nm1 = 0.0f;
    float r_n   = s * invd;

    float h0 = 0.f, h1 = 0.f, h2 = 0.f;
#pragma unroll
    for (int n = 0; n < 8; n++) {
        h0 = fmaf(r_n, T[n * 3 + 0], h0);
        h1 = fmaf(r_n, T[n * 3 + 1], h1);
        h2 = fmaf(r_n, T[n * 3 + 2], h2);
        float r_np1 = fmaf(twoc, r_n, -r_nm1);
        r_nm1 = r_n;
        r_n   = r_np1;
    }

    // shifted-cosine cutoff (rc=5, width=0.5)
    float fc;
    if (d < 4.5f) {
        fc = 1.0f;
    } else if (d < 5.0f) {
        fc = 0.5f * (__cosf(6.28318530717958647692f * (d - 4.5f)) + 1.0f);
    } else {
        fc = 0.0f;
    }

    float f  = fc * invd;
    float y0 = vy * f;   // m order (-1,0,1) -> (y,z,x)/d
    float y1 = vz * f;
    float y2 = vx * f;

    float* base = scratch + (size_t)a * 12;
    // output-ordered: j = m*3+o
    red_add_v4(base + 0, y0 * h0, y0 * h1, y0 * h2, y1 * h0);
    red_add_v4(base + 4, y1 * h1, y1 * h2, y2 * h0, y2 * h1);
    red_add_f32(base + 8, y2 * h2);
}

// One thread per float4 of output (A*9 divisible by 4 when A%4==0).
__global__ void __launch_bounds__(256)
finalize_kernel(const float* __restrict__ scratch, float4* __restrict__ out, int total4)
{
    int i = blockIdx.x * blockDim.x + threadIdx.x;
    if (i >= total4) return;
    int f = i * 4;
    float v[4];
#pragma unroll
    for (int k = 0; k < 4; k++) {
        unsigned ff = f + k;
        unsigned a  = ff / 9u;        // compiler -> mul-hi
        unsigned j  = ff - a * 9u;
        v[k] = scratch[a * 12u + j];
    }
    out[i] = make_float4(v[0], v[1], v[2], v[3]);
}

// fallback for non-multiple-of-4 tails (not expected here, but safe)
__global__ void __launch_bounds__(256)
finalize_tail(const float* __restrict__ scratch, float* __restrict__ out, int start, int total)
{
    int i = start + blockIdx.x * blockDim.x + threadIdx.x;
    if (i >= total) return;
    unsigned a = (unsigned)i / 9u;
    unsigned j = (unsigned)i - a * 9u;
    out[i] = scratch[a * 12u + j];
}

extern "C" void kernel_launch(void* const* d_in, const int* in_sizes, int n_in,
                              void* d_out, int out_size)
{
    const float* vecs      = (const float*)d_in[0];
    const int*   centers   = (const int*)  d_in[1];
    const int*   neighbors = (const int*)  d_in[2];
    const int*   species   = (const int*)  d_in[3];
    // d_in[4] = structures, d_in[5] = atom_index_in_structure: unused by reference
    const float* W_alch    = (const float*)d_in[6];
    const float* emb       = (const float*)d_in[7];
    const float* Wc        = (const float*)d_in[8];

    int E = in_sizes[1];   // centers element count
    int A = in_sizes[3];   // species element count

    float* scratch = nullptr;
    cudaGetSymbolAddress((void**)&scratch, g_scratch);

    cudaMemsetAsync(scratch, 0, (size_t)A * 12 * sizeof(float), 0);

    int blocks = (E + 255) / 256;
    edge_kernel<<<blocks, 256>>>(vecs, centers, neighbors, species,
                                 W_alch, emb, Wc, scratch, E);

    int total  = A * 9;
    int total4 = total / 4;
    if (total4 > 0)
        finalize_kernel<<<(total4 + 255) / 256, 256>>>(scratch, (float4*)d_out, total4);
    int done = total4 * 4;
    if (done < total)
        finalize_tail<<<1, 256>>>(scratch, (float*)d_out, done, total);
}

// round 3
// speedup vs baseline: 1.3954x; 1.3954x over previous
#include <cuda_runtime.h>
#include <cstdint>

// ---------------------------------------------------------------------------
// VectorBasis: out[a,m,o] = sum_{edges e with center a}
//     fc(d_e) * Y_m(e) * sum_n R_n(d_e) * T[sc_a, sn_e, n, o]
// where T[sc,sn,n,o] = sum_q W_alch[sn,q] * emb[sc, n*4+q] * Wc[o, n*4+q]
//
// R1-proven RED pattern: 3x red.global.add.v4.f32 into a (A,12) padded
// scratch (rows m at +0,+4,+8, 4th lane zero). Do NOT narrow (R2 regression).
// ---------------------------------------------------------------------------

#define A_MAX 100000
__device__ float         g_scratch[A_MAX * 12];
__device__ unsigned char g_spec8[A_MAX];

__device__ __forceinline__ void red_add_v4(float* p, float a, float b, float c, float d) {
    asm volatile("red.global.add.v4.f32 [%0], {%1, %2, %3, %4};"
                 :: "l"(p), "f"(a), "f"(b), "f"(c), "f"(d)
                 : "memory");
}

// One pass: zero the scratch (A*12 floats, via float4) and pack species->u8.
__global__ void __launch_bounds__(256)
prep_kernel(const int* __restrict__ species, float4* __restrict__ scratch4,
            unsigned char* __restrict__ spec8, int A)
{
    int i = blockIdx.x * blockDim.x + threadIdx.x;
    int n4 = A * 3;                       // A*12 floats = A*3 float4
    for (int k = i; k < n4; k += gridDim.x * blockDim.x)
        scratch4[k] = make_float4(0.f, 0.f, 0.f, 0.f);
    for (int k = i; k < A; k += gridDim.x * blockDim.x)
        spec8[k] = (unsigned char)species[k];
}

__global__ void __launch_bounds__(256)
edge_kernel(const float*         __restrict__ vecs,     // (E,3)
            const int*           __restrict__ centers,  // (E,)
            const int*           __restrict__ neighbors,// (E,)
            const unsigned char* __restrict__ spec8,    // (A,) packed
            const float*         __restrict__ W_alch,   // (4,4)
            const float*         __restrict__ emb,      // (4,32)
            const float*         __restrict__ Wc,       // (3,32)
            float*               __restrict__ scratch,  // (A,12)
            int E)
{
    // Per-species-pair contraction table, stride 25 (odd -> conflict-free).
    __shared__ float sT[16 * 25];
    __shared__ float sV[256 * 3];
    for (int t = threadIdx.x; t < 16 * 24; t += blockDim.x) {
        int p = t / 24, r = t - p * 24;
        int n = r / 3,  o = r - n * 3;
        int sc = p >> 2, sn = p & 3;
        float v = 0.f;
#pragma unroll
        for (int q = 0; q < 4; q++) {
            int d = n * 4 + q;
            v = fmaf(W_alch[sn * 4 + q] * emb[sc * 32 + d], Wc[o * 32 + d], v);
        }
        sT[p * 25 + r] = v;
    }

    int e0 = blockIdx.x * 256;           // block's first edge
    int t  = threadIdx.x;
    int e  = e0 + t;

    float vx, vy, vz;
    if (e0 + 256 <= E) {
        // full block: stage 256 edges' vectors (768 floats = 192 float4) coalesced
        const float4* v4 = (const float4*)(vecs + (size_t)e0 * 3);
        if (t < 192) ((float4*)sV)[t] = v4[t];
        __syncthreads();
        vx = sV[t * 3 + 0];
        vy = sV[t * 3 + 1];
        vz = sV[t * 3 + 2];
    } else {
        __syncthreads();
        if (e < E) {
            vx = vecs[(size_t)e * 3 + 0];
            vy = vecs[(size_t)e * 3 + 1];
            vz = vecs[(size_t)e * 3 + 2];
        } else {
            vx = vy = vz = 0.f;
        }
        if (e >= E) return;
    }

    float d2   = fmaf(vx, vx, fmaf(vy, vy, vz * vz)) + 1e-12f;
    float invd = rsqrtf(d2);
    float d    = d2 * invd;

    int a  = centers[e];
    int sc = (int)__ldg(&spec8[a]);
    int sn = (int)__ldg(&spec8[neighbors[e]]);
    const float* T = &sT[(sc * 4 + sn) * 25];

    // R_n = sin(n*pi*d/rc)/d via Chebyshev recurrence, invd folded into r1
    float th = 0.62831853071795864769f * d; // pi/5 * d
    float s, c;
    __sincosf(th, &s, &c);
    float twoc = 2.0f * c;
    float r_nm1 = 0.0f;
    float r_n   = s * invd;

    float h0 = 0.f, h1 = 0.f, h2 = 0.f;
#pragma unroll
    for (int n = 0; n < 8; n++) {
        h0 = fmaf(r_n, T[n * 3 + 0], h0);
        h1 = fmaf(r_n, T[n * 3 + 1], h1);
        h2 = fmaf(r_n, T[n * 3 + 2], h2);
        float r_np1 = fmaf(twoc, r_n, -r_nm1);
        r_nm1 = r_n;
        r_n   = r_np1;
    }

    // shifted-cosine cutoff (rc=5, width=0.5)
    float fc;
    if (d < 4.5f) {
        fc = 1.0f;
    } else if (d < 5.0f) {
        fc = 0.5f * (__cosf(6.28318530717958647692f * (d - 4.5f)) + 1.0f);
    } else {
        fc = 0.0f;
    }

    float f  = fc * invd;
    float y0 = vy * f;   // m order (-1,0,1) -> (y,z,x)/d
    float y1 = vz * f;
    float y2 = vx * f;

    float* base = scratch + (size_t)a * 12;
    red_add_v4(base + 0, y0 * h0, y0 * h1, y0 * h2, 0.0f);
    red_add_v4(base + 4, y1 * h0, y1 * h1, y1 * h2, 0.0f);
    red_add_v4(base + 8, y2 * h0, y2 * h1, y2 * h2, 0.0f);
}

// 256 atoms per block. Coalesced float4 loads of scratch, shared repack,
// coalesced float4 stores of out.
__global__ void __launch_bounds__(256)
finalize_kernel(const float4* __restrict__ scratch4, float* __restrict__ out, int A)
{
    __shared__ float sIn[256 * 12];      // 12 KB
    __shared__ float sOut[256 * 9];      // 9 KB
    int a0 = blockIdx.x * 256;
    int t  = threadIdx.x;
    int valid = A - a0; if (valid > 256) valid = 256;

    // load valid*3 float4s coalesced
    int nf4 = valid * 3;
#pragma unroll
    for (int k = 0; k < 3; k++) {
        int idx = t + 256 * k;
        if (idx < nf4) ((float4*)sIn)[idx] = scratch4[(size_t)a0 * 3 + idx];
    }
    __syncthreads();

    // repack: atom t's 9 values (j = m*3+o) from slot layout m*4+o
    if (t < valid) {
#pragma unroll
        for (int m = 0; m < 3; m++)
#pragma unroll
            for (int o = 0; o < 3; o++)
                sOut[t * 9 + m * 3 + o] = sIn[t * 12 + m * 4 + o];
    }
    __syncthreads();

    // store valid*9 floats coalesced
    if (valid == 256) {
        // 2304 floats = 576 float4, base a0*36 bytes is 16B-aligned (a0%256==0)
        float4* o4 = (float4*)(out + (size_t)a0 * 9);
#pragma unroll
        for (int k = 0; k < 3; k++) {
            int idx = t + 256 * k;
            if (idx < 576) o4[idx] = ((float4*)sOut)[idx];
        }
    } else {
        int nf = valid * 9;
        for (int idx = t; idx < nf; idx += 256)
            out[(size_t)a0 * 9 + idx] = sOut[idx];
    }
}

extern "C" void kernel_launch(void* const* d_in, const int* in_sizes, int n_in,
                              void* d_out, int out_size)
{
    const float* vecs      = (const float*)d_in[0];
    const int*   centers   = (const int*)  d_in[1];
    const int*   neighbors = (const int*)  d_in[2];
    const int*   species   = (const int*)  d_in[3];
    // d_in[4] = structures, d_in[5] = atom_index_in_structure: unused by reference
    const float* W_alch    = (const float*)d_in[6];
    const float* emb       = (const float*)d_in[7];
    const float* Wc        = (const float*)d_in[8];

    int E = in_sizes[1];   // centers element count
    int A = in_sizes[3];   // species element count

    float* scratch = nullptr;
    cudaGetSymbolAddress((void**)&scratch, g_scratch);
    unsigned char* spec8 = nullptr;
    cudaGetSymbolAddress((void**)&spec8, g_spec8);

    prep_kernel<<<592, 256>>>(species, (float4*)scratch, spec8, A);

    int blocks = (E + 255) / 256;
    edge_kernel<<<blocks, 256>>>(vecs, centers, neighbors, spec8,
                                 W_alch, emb, Wc, scratch, E);

    int ablocks = (A + 255) / 256;
    finalize_kernel<<<ablocks, 256>>>((const float4*)scratch, (float*)d_out, A);
}